// round 1
// baseline (speedup 1.0000x reference)
#include <cuda_runtime.h>
#include <cuda_bf16.h>
#include <cstdint>

#define N_NODES  100000
#define N_EDGES  1600000
#define N_GRAPHS 128
#define D        64
#define SCAN_B   1024
#define NB_SCAN  ((N_NODES + SCAN_B - 1) / SCAN_B)   // 98

// ---------------- device scratch (no allocations allowed) ----------------
__device__ int   g_deg[N_NODES];
__device__ int   g_off[N_NODES + 1];
__device__ int   g_cursor[N_NODES];
__device__ int   g_bsums[128];
__device__ int   g_csr[N_EDGES];
__device__ float g_f [N_NODES * D];   // f  (layer-1 softmax output)
__device__ float g_nf[N_NODES * D];   // new_f = f + layer-2 softmax output
__device__ float g_fg [N_GRAPHS * D];
__device__ float g_nfg[N_GRAPHS * D];

// ---------------- CSR build ----------------
__global__ void k_zero_deg() {
    int i = blockIdx.x * blockDim.x + threadIdx.x;
    if (i < N_NODES) g_deg[i] = 0;
}

__global__ void k_hist(const int* __restrict__ dst) {
    int e = blockIdx.x * blockDim.x + threadIdx.x;
    if (e < N_EDGES) atomicAdd(&g_deg[dst[e]], 1);
}

__global__ void k_scan1() {
    __shared__ int s[SCAN_B];
    int tid = threadIdx.x;
    int i = blockIdx.x * SCAN_B + tid;
    int v = (i < N_NODES) ? g_deg[i] : 0;
    s[tid] = v;
    __syncthreads();
    #pragma unroll
    for (int o = 1; o < SCAN_B; o <<= 1) {
        int t = (tid >= o) ? s[tid - o] : 0;
        __syncthreads();
        s[tid] += t;
        __syncthreads();
    }
    if (i < N_NODES) g_off[i] = s[tid] - v;          // block-local exclusive
    if (tid == SCAN_B - 1) g_bsums[blockIdx.x] = s[tid];
}

__global__ void k_scan2() {
    __shared__ int s[128];
    int tid = threadIdx.x;
    if (tid < NB_SCAN) s[tid] = g_bsums[tid];
    __syncthreads();
    if (tid == 0) {
        int run = 0;
        for (int b = 0; b < NB_SCAN; b++) { int t = s[b]; s[b] = run; run += t; }
    }
    __syncthreads();
    if (tid < NB_SCAN) g_bsums[tid] = s[tid];
}

__global__ void k_scan3() {
    int i = blockIdx.x * blockDim.x + threadIdx.x;
    if (i < N_NODES) {
        int o = g_off[i] + g_bsums[i >> 10];
        g_off[i] = o;
        g_cursor[i] = o;
    }
    if (i == 0) g_off[N_NODES] = N_EDGES;
}

__global__ void k_scatter(const int* __restrict__ src, const int* __restrict__ dst) {
    int e = blockIdx.x * blockDim.x + threadIdx.x;
    if (e < N_EDGES) {
        int d = dst[e];
        int pos = atomicAdd(&g_cursor[d], 1);
        g_csr[pos] = src[e];
    }
}

// ---------------- fused layer: mean-aggregate -> GEMM+ReLU -> GEMM+softmax (-> +residual) ----------------
// warp per node, 8 warps/block, 8 nodes/warp => 64 nodes/block
__global__ __launch_bounds__(256, 4)
void k_layer(int layer,
             const float* __restrict__ feat,
             const float* __restrict__ W1, const float* __restrict__ b1,
             const float* __restrict__ Ws, const float* __restrict__ bs) {
    __shared__ __align__(16) float sW1[D * D];
    __shared__ __align__(16) float sWs[D * D];
    __shared__ float sb1[D], sbs[D];

    int tid = threadIdx.x;
    for (int i = tid; i < D * D; i += 256) { sW1[i] = W1[i]; sWs[i] = Ws[i]; }
    if (tid < D) { sb1[tid] = b1[tid]; sbs[tid] = bs[tid]; }
    __syncthreads();

    const float* in   = (layer == 0) ? feat : g_f;
    float*       out  = (layer == 0) ? g_f  : g_nf;
    const unsigned FULL = 0xffffffffu;
    int warp = tid >> 5, lane = tid & 31;
    int base = (blockIdx.x * 8 + warp) * 8;

    for (int n = base; n < base + 8 && n < N_NODES; n++) {
        int s0 = g_off[n], s1 = g_off[n + 1];
        int deg = s1 - s0;

        // ---- mean aggregation over incoming edges ----
        float2 acc = make_float2(0.f, 0.f);
        for (int e0 = s0; e0 < s1; e0 += 32) {
            int idx = (e0 + lane < s1) ? g_csr[e0 + lane] : 0;
            int cnt = min(32, s1 - e0);
            for (int j = 0; j < cnt; j++) {
                int srow = __shfl_sync(FULL, idx, j);
                float2 v = ((const float2*)(in + (size_t)srow * D))[lane];
                acc.x += v.x; acc.y += v.y;
            }
        }
        if (deg > 0) {
            float inv = 1.0f / (float)deg;
            acc.x *= inv; acc.y *= inv;
        } else {
            acc = ((const float2*)(in + (size_t)n * D))[lane];
        }

        // ---- GEMM1 + bias + ReLU ----
        float2 h = make_float2(sb1[2 * lane], sb1[2 * lane + 1]);
        #pragma unroll
        for (int k = 0; k < D; k++) {
            float a = __shfl_sync(FULL, (k & 1) ? acc.y : acc.x, k >> 1);
            float2 w = ((const float2*)(sW1 + k * D))[lane];
            h.x = fmaf(a, w.x, h.x);
            h.y = fmaf(a, w.y, h.y);
        }
        h.x = fmaxf(h.x, 0.f); h.y = fmaxf(h.y, 0.f);

        // ---- GEMM2 + bias ----
        float2 l = make_float2(sbs[2 * lane], sbs[2 * lane + 1]);
        #pragma unroll
        for (int k = 0; k < D; k++) {
            float a = __shfl_sync(FULL, (k & 1) ? h.y : h.x, k >> 1);
            float2 w = ((const float2*)(sWs + k * D))[lane];
            l.x = fmaf(a, w.x, l.x);
            l.y = fmaf(a, w.y, l.y);
        }

        // ---- softmax over 64 features ----
        float m = fmaxf(l.x, l.y);
        #pragma unroll
        for (int o = 16; o > 0; o >>= 1) m = fmaxf(m, __shfl_xor_sync(FULL, m, o));
        float e0 = __expf(l.x - m), e1 = __expf(l.y - m);
        float s = e0 + e1;
        #pragma unroll
        for (int o = 16; o > 0; o >>= 1) s += __shfl_xor_sync(FULL, s, o);
        float invs = 1.0f / s;
        float2 p = make_float2(e0 * invs, e1 * invs);

        if (layer != 0) {   // new_f = f + p
            float2 r = ((const float2*)(g_f + (size_t)n * D))[lane];
            p.x += r.x; p.y += r.y;
        }
        ((float2*)(out + (size_t)n * D))[lane] = p;
    }
}

// ---------------- graph sum pooling (graph_ids sorted -> binary search, no atomics) ----------------
__device__ __forceinline__ int lower_bound(const int* a, int n, int key) {
    int lo = 0, hi = n;
    while (lo < hi) { int m = (lo + hi) >> 1; if (a[m] < key) lo = m + 1; else hi = m; }
    return lo;
}

__global__ void k_pool(const int* __restrict__ gid) {
    int g = blockIdx.x;
    int lo = lower_bound(gid, N_NODES, g);
    int hi = lower_bound(gid, N_NODES, g + 1);
    int tid = threadIdx.x;
    int j = tid & 63, r = tid >> 6;       // 4 row-lanes, 64 features
    float a = 0.f, b = 0.f;
    for (int n = lo + r; n < hi; n += 4) {
        a += g_f [(size_t)n * D + j];
        b += g_nf[(size_t)n * D + j];
    }
    __shared__ float sa[4][64], sb[4][64];
    sa[r][j] = a; sb[r][j] = b;
    __syncthreads();
    if (tid < 64) {
        g_fg [g * D + tid] = sa[0][tid] + sa[1][tid] + sa[2][tid] + sa[3][tid];
        g_nfg[g * D + tid] = sb[0][tid] + sb[1][tid] + sb[2][tid] + sb[3][tid];
    }
}

// ---------------- head: relu(cat(fg,new_fg) @ Wd + bd) @ Wc + bc ----------------
__global__ void k_head(const float* __restrict__ Wd, const float* __restrict__ bd,
                       const float* __restrict__ Wc, const float* __restrict__ bc,
                       float* __restrict__ out) {
    int g = blockIdx.x;
    int j = threadIdx.x;          // 64 threads
    __shared__ float cat[2 * D];
    cat[j]     = g_fg [g * D + j];
    cat[j + D] = g_nfg[g * D + j];
    __syncthreads();
    float acc = bd[j];
    #pragma unroll
    for (int k = 0; k < 2 * D; k++) acc = fmaf(cat[k], Wd[k * D + j], acc);
    acc = fmaxf(acc, 0.f);
    float part = acc * Wc[j];
    const unsigned FULL = 0xffffffffu;
    #pragma unroll
    for (int o = 16; o > 0; o >>= 1) part += __shfl_xor_sync(FULL, part, o);
    __shared__ float red[2];
    if ((j & 31) == 0) red[j >> 5] = part;
    __syncthreads();
    if (j == 0) out[g] = red[0] + red[1] + bc[0];
}

// ---------------- launch ----------------
extern "C" void kernel_launch(void* const* d_in, const int* in_sizes, int n_in,
                              void* d_out, int out_size) {
    const float* feat = (const float*)d_in[0];
    const int*   src  = (const int*)  d_in[1];
    const int*   dst  = (const int*)  d_in[2];
    const int*   gid  = (const int*)  d_in[3];
    const float* W1   = (const float*)d_in[4];
    const float* b1   = (const float*)d_in[5];
    const float* Ws1  = (const float*)d_in[6];
    const float* bs1  = (const float*)d_in[7];
    const float* W2   = (const float*)d_in[8];
    const float* b2   = (const float*)d_in[9];
    const float* Ws2  = (const float*)d_in[10];
    const float* bs2  = (const float*)d_in[11];
    const float* Wd   = (const float*)d_in[12];
    const float* bd   = (const float*)d_in[13];
    const float* Wc   = (const float*)d_in[14];
    const float* bc   = (const float*)d_in[15];
    float* out = (float*)d_out;

    // CSR build (shared by both aggregation passes)
    k_zero_deg<<<(N_NODES + 255) / 256, 256>>>();
    k_hist<<<(N_EDGES + 255) / 256, 256>>>(dst);
    k_scan1<<<NB_SCAN, SCAN_B>>>();
    k_scan2<<<1, 128>>>();
    k_scan3<<<(N_NODES + 255) / 256, 256>>>();
    k_scatter<<<(N_EDGES + 255) / 256, 256>>>(src, dst);

    // layer 1: feat -> f ;  layer 2: f -> new_f (with residual)
    int layer_grid = (N_NODES + 63) / 64;
    k_layer<<<layer_grid, 256>>>(0, feat, W1, b1, Ws1, bs1);
    k_layer<<<layer_grid, 256>>>(1, feat, W2, b2, Ws2, bs2);

    k_pool<<<N_GRAPHS, 256>>>(gid);
    k_head<<<N_GRAPHS, 64>>>(Wd, bd, Wc, bc, out);
    (void)in_sizes; (void)n_in; (void)out_size;
}

// round 2
// speedup vs baseline: 1.1908x; 1.1908x over previous
#include <cuda_runtime.h>
#include <cuda_bf16.h>
#include <cstdint>

#define N_NODES  100000
#define N_EDGES  1600000
#define N_GRAPHS 128
#define D        64
#define SCAN_B   1024
#define NB_SCAN  ((N_NODES + SCAN_B - 1) / SCAN_B)   // 98
#define NT       4          // nodes per warp in k_layer
#define LW       4          // warps per block in k_layer

typedef unsigned long long ull;

// ---------------- device scratch (no allocations allowed) ----------------
__device__ int   g_deg[N_NODES];
__device__ int   g_off[N_NODES + 1];
__device__ int   g_cursor[N_NODES];
__device__ int   g_bsums[128];
__device__ int   g_csr[N_EDGES];
__device__ float g_f [N_NODES * D];   // f  (layer-1 softmax output)
__device__ float g_nf[N_NODES * D];   // new_f = f + layer-2 softmax output
__device__ float g_fg [N_GRAPHS * D];
__device__ float g_nfg[N_GRAPHS * D];

// ---------------- packed fp32x2 helpers (sm_100a) ----------------
__device__ __forceinline__ ull ffma2(ull a, ull b, ull c) {
    ull d;
    asm("fma.rn.f32x2 %0, %1, %2, %3;" : "=l"(d) : "l"(a), "l"(b), "l"(c));
    return d;
}
__device__ __forceinline__ ull pack2(float x, float y) {
    ull r; asm("mov.b64 %0, {%1, %2};" : "=l"(r) : "f"(x), "f"(y)); return r;
}
__device__ __forceinline__ void unpack2(ull v, float& x, float& y) {
    asm("mov.b64 {%0, %1}, %2;" : "=f"(x), "=f"(y) : "l"(v));
}

// ---------------- CSR build ----------------
__global__ void k_zero_deg() {
    int i = blockIdx.x * blockDim.x + threadIdx.x;
    if (i < N_NODES) g_deg[i] = 0;
}

__global__ void k_hist(const int* __restrict__ dst) {
    int e = blockIdx.x * blockDim.x + threadIdx.x;
    if (e < N_EDGES) atomicAdd(&g_deg[dst[e]], 1);
}

__global__ void k_scan1() {
    __shared__ int s[SCAN_B];
    int tid = threadIdx.x;
    int i = blockIdx.x * SCAN_B + tid;
    int v = (i < N_NODES) ? g_deg[i] : 0;
    s[tid] = v;
    __syncthreads();
    #pragma unroll
    for (int o = 1; o < SCAN_B; o <<= 1) {
        int t = (tid >= o) ? s[tid - o] : 0;
        __syncthreads();
        s[tid] += t;
        __syncthreads();
    }
    if (i < N_NODES) g_off[i] = s[tid] - v;
    if (tid == SCAN_B - 1) g_bsums[blockIdx.x] = s[tid];
}

__global__ void k_scan2() {
    __shared__ int s[128];
    int tid = threadIdx.x;
    if (tid < NB_SCAN) s[tid] = g_bsums[tid];
    __syncthreads();
    if (tid == 0) {
        int run = 0;
        for (int b = 0; b < NB_SCAN; b++) { int t = s[b]; s[b] = run; run += t; }
    }
    __syncthreads();
    if (tid < NB_SCAN) g_bsums[tid] = s[tid];
}

__global__ void k_scan3() {
    int i = blockIdx.x * blockDim.x + threadIdx.x;
    if (i < N_NODES) {
        int o = g_off[i] + g_bsums[i >> 10];
        g_off[i] = o;
        g_cursor[i] = o;
    }
    if (i == 0) g_off[N_NODES] = N_EDGES;
}

__global__ void k_scatter(const int* __restrict__ src, const int* __restrict__ dst) {
    int e = blockIdx.x * blockDim.x + threadIdx.x;
    if (e < N_EDGES) {
        int d = dst[e];
        int pos = atomicAdd(&g_cursor[d], 1);
        g_csr[pos] = src[e];
    }
}

// ---------------- fused layer ----------------
// 4 warps/block, 4 nodes/warp. Aggregated rows stored to smem DUPLICATED
// ({a,a} pairs) so GEMM reads them as broadcast LDS.64 directly usable by FFMA2.
__global__ __launch_bounds__(32 * LW, 5)
void k_layer(int layer,
             const float* __restrict__ feat,
             const float* __restrict__ W1, const float* __restrict__ b1,
             const float* __restrict__ Ws, const float* __restrict__ bs) {
    __shared__ __align__(16) float sW1[D * D];
    __shared__ __align__(16) float sWs[D * D];
    __shared__ float sb1[D], sbs[D];
    __shared__ __align__(16) float sA[LW][NT][2 * D];   // duplicated activations

    int tid = threadIdx.x;
    for (int i = tid; i < D * D; i += 32 * LW) { sW1[i] = W1[i]; sWs[i] = Ws[i]; }
    if (tid < D) { sb1[tid] = b1[tid]; sbs[tid] = bs[tid]; }
    __syncthreads();

    const float* in  = (layer == 0) ? feat : g_f;
    float*       out = (layer == 0) ? g_f  : g_nf;
    const unsigned FULL = 0xffffffffu;
    int warp = tid >> 5, lane = tid & 31;
    int base = (blockIdx.x * LW + warp) * NT;

    // ---- mean aggregation for NT nodes, unrolled for MLP ----
    #pragma unroll
    for (int t = 0; t < NT; t++) {
        int n = base + t;
        float2 acc = make_float2(0.f, 0.f);
        int s0 = 0, s1 = 0;
        if (n < N_NODES) { s0 = g_off[n]; s1 = g_off[n + 1]; }
        int deg = s1 - s0;
        for (int e0 = s0; e0 < s1; e0 += 32) {
            int ecnt = min(32, s1 - e0);
            int idx = (lane < ecnt) ? g_csr[e0 + lane] : 0;
            int j = 0;
            for (; j + 8 <= ecnt; j += 8) {
                int r0 = __shfl_sync(FULL, idx, j + 0);
                int r1 = __shfl_sync(FULL, idx, j + 1);
                int r2 = __shfl_sync(FULL, idx, j + 2);
                int r3 = __shfl_sync(FULL, idx, j + 3);
                int r4 = __shfl_sync(FULL, idx, j + 4);
                int r5 = __shfl_sync(FULL, idx, j + 5);
                int r6 = __shfl_sync(FULL, idx, j + 6);
                int r7 = __shfl_sync(FULL, idx, j + 7);
                float2 v0 = ((const float2*)(in + (size_t)r0 * D))[lane];
                float2 v1 = ((const float2*)(in + (size_t)r1 * D))[lane];
                float2 v2 = ((const float2*)(in + (size_t)r2 * D))[lane];
                float2 v3 = ((const float2*)(in + (size_t)r3 * D))[lane];
                float2 v4 = ((const float2*)(in + (size_t)r4 * D))[lane];
                float2 v5 = ((const float2*)(in + (size_t)r5 * D))[lane];
                float2 v6 = ((const float2*)(in + (size_t)r6 * D))[lane];
                float2 v7 = ((const float2*)(in + (size_t)r7 * D))[lane];
                acc.x += v0.x + v1.x + v2.x + v3.x + v4.x + v5.x + v6.x + v7.x;
                acc.y += v0.y + v1.y + v2.y + v3.y + v4.y + v5.y + v6.y + v7.y;
            }
            for (; j < ecnt; j++) {
                int r = __shfl_sync(FULL, idx, j);
                float2 v = ((const float2*)(in + (size_t)r * D))[lane];
                acc.x += v.x; acc.y += v.y;
            }
        }
        if (deg > 0) {
            float inv = 1.0f / (float)deg;
            acc.x *= inv; acc.y *= inv;
        } else if (n < N_NODES) {
            acc = ((const float2*)(in + (size_t)n * D))[lane];
        }
        ((float4*)&sA[warp][t][4 * lane])[0] = make_float4(acc.x, acc.x, acc.y, acc.y);
    }
    __syncwarp();

    // ---- GEMM1 + bias + ReLU (FFMA2, weights shared across NT nodes) ----
    ull h[NT];
    {
        ull hb = pack2(sb1[2 * lane], sb1[2 * lane + 1]);
        #pragma unroll
        for (int t = 0; t < NT; t++) h[t] = hb;
        #pragma unroll
        for (int k = 0; k < D; k++) {
            ull w = *(const ull*)(sW1 + k * D + 2 * lane);
            #pragma unroll
            for (int t = 0; t < NT; t++) {
                ull a = *(const ull*)&sA[warp][t][2 * k];
                h[t] = ffma2(a, w, h[t]);
            }
        }
    }
    __syncwarp();
    #pragma unroll
    for (int t = 0; t < NT; t++) {
        float hx, hy; unpack2(h[t], hx, hy);
        hx = fmaxf(hx, 0.f); hy = fmaxf(hy, 0.f);
        ((float4*)&sA[warp][t][4 * lane])[0] = make_float4(hx, hx, hy, hy);
    }
    __syncwarp();

    // ---- GEMM2 + bias ----
    ull l[NT];
    {
        ull lb = pack2(sbs[2 * lane], sbs[2 * lane + 1]);
        #pragma unroll
        for (int t = 0; t < NT; t++) l[t] = lb;
        #pragma unroll
        for (int k = 0; k < D; k++) {
            ull w = *(const ull*)(sWs + k * D + 2 * lane);
            #pragma unroll
            for (int t = 0; t < NT; t++) {
                ull a = *(const ull*)&sA[warp][t][2 * k];
                l[t] = ffma2(a, w, l[t]);
            }
        }
    }

    // ---- softmax (+ residual for layer 2) ----
    #pragma unroll
    for (int t = 0; t < NT; t++) {
        int n = base + t;
        float lx, ly; unpack2(l[t], lx, ly);
        float m = fmaxf(lx, ly);
        #pragma unroll
        for (int o = 16; o > 0; o >>= 1) m = fmaxf(m, __shfl_xor_sync(FULL, m, o));
        float e0 = __expf(lx - m), e1 = __expf(ly - m);
        float s = e0 + e1;
        #pragma unroll
        for (int o = 16; o > 0; o >>= 1) s += __shfl_xor_sync(FULL, s, o);
        float invs = 1.0f / s;
        float2 p = make_float2(e0 * invs, e1 * invs);
        if (n < N_NODES) {
            if (layer != 0) {
                float2 r = ((const float2*)(g_f + (size_t)n * D))[lane];
                p.x += r.x; p.y += r.y;
            }
            ((float2*)(out + (size_t)n * D))[lane] = p;
        }
    }
}

// ---------------- graph sum pooling ----------------
__device__ __forceinline__ int lower_bound(const int* a, int n, int key) {
    int lo = 0, hi = n;
    while (lo < hi) { int m = (lo + hi) >> 1; if (a[m] < key) lo = m + 1; else hi = m; }
    return lo;
}

__global__ void k_pool(const int* __restrict__ gid) {
    int g = blockIdx.x;
    int lo = lower_bound(gid, N_NODES, g);
    int hi = lower_bound(gid, N_NODES, g + 1);
    int tid = threadIdx.x;
    int j = tid & 63, r = tid >> 6;
    float a = 0.f, b = 0.f;
    for (int n = lo + r; n < hi; n += 4) {
        a += g_f [(size_t)n * D + j];
        b += g_nf[(size_t)n * D + j];
    }
    __shared__ float sa[4][64], sb[4][64];
    sa[r][j] = a; sb[r][j] = b;
    __syncthreads();
    if (tid < 64) {
        g_fg [g * D + tid] = sa[0][tid] + sa[1][tid] + sa[2][tid] + sa[3][tid];
        g_nfg[g * D + tid] = sb[0][tid] + sb[1][tid] + sb[2][tid] + sb[3][tid];
    }
}

// ---------------- head ----------------
__global__ void k_head(const float* __restrict__ Wd, const float* __restrict__ bd,
                       const float* __restrict__ Wc, const float* __restrict__ bc,
                       float* __restrict__ out) {
    int g = blockIdx.x;
    int j = threadIdx.x;          // 64 threads
    __shared__ float cat[2 * D];
    cat[j]     = g_fg [g * D + j];
    cat[j + D] = g_nfg[g * D + j];
    __syncthreads();
    float acc = bd[j];
    #pragma unroll
    for (int k = 0; k < 2 * D; k++) acc = fmaf(cat[k], Wd[k * D + j], acc);
    acc = fmaxf(acc, 0.f);
    float part = acc * Wc[j];
    const unsigned FULL = 0xffffffffu;
    #pragma unroll
    for (int o = 16; o > 0; o >>= 1) part += __shfl_xor_sync(FULL, part, o);
    __shared__ float red[2];
    if ((j & 31) == 0) red[j >> 5] = part;
    __syncthreads();
    if (j == 0) out[g] = red[0] + red[1] + bc[0];
}

// ---------------- launch ----------------
extern "C" void kernel_launch(void* const* d_in, const int* in_sizes, int n_in,
                              void* d_out, int out_size) {
    const float* feat = (const float*)d_in[0];
    const int*   src  = (const int*)  d_in[1];
    const int*   dst  = (const int*)  d_in[2];
    const int*   gid  = (const int*)  d_in[3];
    const float* W1   = (const float*)d_in[4];
    const float* b1   = (const float*)d_in[5];
    const float* Ws1  = (const float*)d_in[6];
    const float* bs1  = (const float*)d_in[7];
    const float* W2   = (const float*)d_in[8];
    const float* b2   = (const float*)d_in[9];
    const float* Ws2  = (const float*)d_in[10];
    const float* bs2  = (const float*)d_in[11];
    const float* Wd   = (const float*)d_in[12];
    const float* bd   = (const float*)d_in[13];
    const float* Wc   = (const float*)d_in[14];
    const float* bc   = (const float*)d_in[15];
    float* out = (float*)d_out;

    k_zero_deg<<<(N_NODES + 255) / 256, 256>>>();
    k_hist<<<(N_EDGES + 255) / 256, 256>>>(dst);
    k_scan1<<<NB_SCAN, SCAN_B>>>();
    k_scan2<<<1, 128>>>();
    k_scan3<<<(N_NODES + 255) / 256, 256>>>();
    k_scatter<<<(N_EDGES + 255) / 256, 256>>>(src, dst);

    int nodes_per_block = LW * NT;   // 16
    int layer_grid = (N_NODES + nodes_per_block - 1) / nodes_per_block;
    k_layer<<<layer_grid, 32 * LW>>>(0, feat, W1, b1, Ws1, bs1);
    k_layer<<<layer_grid, 32 * LW>>>(1, feat, W2, b2, Ws2, bs2);

    k_pool<<<N_GRAPHS, 256>>>(gid);
    k_head<<<N_GRAPHS, 64>>>(Wd, bd, Wc, bc, out);
    (void)in_sizes; (void)n_in; (void)out_size;
}